// round 4
// baseline (speedup 1.0000x reference)
#include <cuda_runtime.h>
#include <cstdint>

#define NN 100000
#define FF 64
#define NODES 4

// ---------------- scratch (device globals: no runtime allocation) ----------
__device__ float g_sum_pos[(size_t)NN * FF];
__device__ float g_sum_neg[(size_t)NN * FF];
__device__ float g_cnt_pos[NN];
__device__ float g_cnt_neg[NN];
__device__ float g_hb[136]; // [0:64) hb_pos, [64:128) hb_neg, [128] y2_pos, [129] y2_neg

__device__ __forceinline__ float wsum(float v) {
#pragma unroll
    for (int o = 16; o > 0; o >>= 1) v += __shfl_xor_sync(0xffffffffu, v, o);
    return v;
}

// packed f32x2 helpers (sm_103a)
__device__ __forceinline__ unsigned long long fma2(unsigned long long a,
                                                   unsigned long long b,
                                                   unsigned long long c) {
    unsigned long long d;
    asm("fma.rn.f32x2 %0, %1, %2, %3;" : "=l"(d) : "l"(a), "l"(b), "l"(c));
    return d;
}
__device__ __forceinline__ unsigned long long pack2(float v) {
    unsigned long long d;
    asm("mov.b64 %0, {%1, %1};" : "=l"(d) : "r"(__float_as_uint(v)));
    return d;
}
__device__ __forceinline__ float2 unpack2(unsigned long long a) {
    unsigned int lo, hi;
    asm("mov.b64 {%0, %1}, %2;" : "=r"(lo), "=r"(hi) : "l"(a));
    return make_float2(__uint_as_float(lo), __uint_as_float(hi));
}

// ---------------- hyperbolic bias precompute: proj(expmap0(b, c=1)) --------
__global__ void bias_kernel(const float* __restrict__ bp, const float* __restrict__ bn) {
    int lane = threadIdx.x;
    if (lane >= 32) return;
    const float* bs[2] = {bp, bn};
#pragma unroll
    for (int i = 0; i < 2; ++i) {
        float u0 = bs[i][lane], u1 = bs[i][lane + 32];
        float n = fmaxf(sqrtf(wsum(u0 * u0 + u1 * u1)), 1e-15f);
        float s = tanhf(n) / n;
        float v0 = u0 * s, v1 = u1 * s;
        float vn = fmaxf(sqrtf(wsum(v0 * v0 + v1 * v1)), 1e-15f);
        if (vn > 0.996f) { float p = 0.996f / vn; v0 *= p; v1 *= p; }
        g_hb[i * 64 + lane]      = v0;
        g_hb[i * 64 + 32 + lane] = v1;
        float y2 = wsum(v0 * v0 + v1 * v1);
        if (lane == 0) g_hb[128 + i] = y2;
    }
}

// ---------------- merged scatter-sum + count over both edge lists ----------
// 16 threads per edge (one 16B chunk each); vectorized red.global.
__global__ void scatter_kernel(const float* __restrict__ x,
                               const int* __restrict__ pei, const int* __restrict__ nei,
                               float* __restrict__ sp, float* __restrict__ sn,
                               float* __restrict__ cp, float* __restrict__ cn, int E) {
    long tid = (long)blockIdx.x * blockDim.x + threadIdx.x;
    long e2 = tid >> 4;
    int ch = (int)(tid & 15);
    if (e2 >= 2L * E) return;
    bool neg = e2 >= E;
    long e = neg ? e2 - E : e2;
    const int* ei = neg ? nei : pei;
    float* sum = neg ? sn : sp;
    float* cnt = neg ? cn : cp;
    int src = ei[e];
    int dst = ei[(long)E + e];
    float4 v = *reinterpret_cast<const float4*>(x + (size_t)src * FF + ch * 4);
    float* a = sum + (size_t)dst * FF + ch * 4;
    asm volatile("red.global.add.v4.f32 [%0], {%1,%2,%3,%4};"
                 :: "l"(a), "f"(v.x), "f"(v.y), "f"(v.z), "f"(v.w) : "memory");
    if (ch == 0) atomicAdd(cnt + dst, 1.0f);
}

// ---------------- mobius_matvec + proj (c = 1) -----------------------------
__device__ __forceinline__ void matvec_proj(float m0, float m1, float xn,
                                            float& r0, float& r1) {
    float msq = wsum(m0 * m0 + m1 * m1);
    float mn = fmaxf(sqrtf(msq), 1e-15f);
    float art = atanhf(fminf(xn, 1.0f - 1e-7f));
    float sc = tanhf(mn / xn * art) / mn;
    r0 = m0 * sc; r1 = m1 * sc;
    float rsq = wsum(r0 * r0 + r1 * r1);
    float rn = fmaxf(sqrtf(rsq), 1e-15f);
    if (rn > 0.996f) { float s = 0.996f / rn; r0 *= s; r1 *= s; }
}

// out = proj(matvec(agg)) + proj(mobius_add(proj(matvec(x)), hyp_bias))
__device__ __forceinline__ void node_out(
    float aP0, float aP1, float pn,
    float aC0, float aC1, float xn,
    float hb0, float hb1, float y2,
    float& o0, float& o1) {
    float r0, r1; matvec_proj(aP0, aP1, pn, r0, r1);
    float s0, s1; matvec_proj(aC0, aC1, xn, s0, s1);
    float x2 = wsum(s0 * s0 + s1 * s1);
    float xy = wsum(s0 * hb0 + s1 * hb1);
    float f1 = 1.0f + 2.0f * xy + y2;
    float f2 = 1.0f - x2;
    float den = fmaxf(1.0f + 2.0f * xy + x2 * y2, 1e-15f);
    float q0 = (f1 * s0 + f2 * hb0) / den;
    float q1 = (f1 * s1 + f2 * hb1) / den;
    float qn = fmaxf(sqrtf(wsum(q0 * q0 + q1 * q1)), 1e-15f);
    if (qn > 0.996f) { float p = 0.996f / qn; q0 *= p; q1 *= p; }
    o0 = r0 + q0; o1 = r1 + q1;
}

// ---------------- main per-node kernel: warp handles 4 nodes ---------------
// Weights in smem packed as float2: sh2[m*2112 + k*33 + o] = {W[o][k], W[o+32][k]}
__global__ void __launch_bounds__(256, 2)
compute_kernel(const float* __restrict__ x,
               const float* __restrict__ Wp,  const float* __restrict__ Wpc,
               const float* __restrict__ Wn,  const float* __restrict__ Wnc,
               float* __restrict__ out, int n) {
    extern __shared__ float2 sh2[];
    {
        const float* Ws[4] = {Wp, Wpc, Wn, Wnc};
#pragma unroll
        for (int m = 0; m < 4; ++m) {
            const float* W = Ws[m];
            for (int idx = threadIdx.x; idx < 2048; idx += blockDim.x) {
                int k = idx >> 5, o = idx & 31;
                sh2[m * 2112 + k * 33 + o] = make_float2(W[o * 64 + k], W[(o + 32) * 64 + k]);
            }
        }
    }
    __syncthreads();

    const unsigned long long* wPp = (const unsigned long long*)(sh2);
    const unsigned long long* wPc = (const unsigned long long*)(sh2 + 2112);
    const unsigned long long* wNp = (const unsigned long long*)(sh2 + 2 * 2112);
    const unsigned long long* wNc = (const unsigned long long*)(sh2 + 3 * 2112);

    const unsigned FULL = 0xffffffffu;
    int lane = threadIdx.x & 31;
    int gw = (int)((blockIdx.x * blockDim.x + threadIdx.x) >> 5);
    int nw = (int)((gridDim.x * blockDim.x) >> 5);

    float hbp0 = g_hb[lane],      hbp1 = g_hb[32 + lane];
    float hbn0 = g_hb[64 + lane], hbn1 = g_hb[96 + lane];
    float y2p = g_hb[128], y2n = g_hb[129];

    for (long i0 = (long)gw * NODES; i0 < n; i0 += (long)nw * NODES) {
        long idx[NODES];
        bool valid[NODES];
        float x0v[NODES], x1v[NODES], p0v[NODES], p1v[NODES], n0v[NODES], n1v[NODES];
#pragma unroll
        for (int r = 0; r < NODES; ++r) {
            long i = i0 + r;
            valid[r] = (i < n);
            if (i >= n) i = n - 1;
            idx[r] = i;
            x0v[r] = x[i * 64 + lane];
            x1v[r] = x[i * 64 + 32 + lane];
            float rp = 1.0f / fmaxf(g_cnt_pos[i], 1.0f);
            float rn = 1.0f / fmaxf(g_cnt_neg[i], 1.0f);
            p0v[r] = g_sum_pos[i * 64 + lane] * rp;
            p1v[r] = g_sum_pos[i * 64 + 32 + lane] * rp;
            n0v[r] = g_sum_neg[i * 64 + lane] * rn;
            n1v[r] = g_sum_neg[i * 64 + 32 + lane] * rn;
        }

        unsigned long long aPp[NODES], aPc[NODES], aNp[NODES], aNc[NODES];
#pragma unroll
        for (int r = 0; r < NODES; ++r) { aPp[r] = 0ull; aPc[r] = 0ull; aNp[r] = 0ull; aNc[r] = 0ull; }

#pragma unroll
        for (int half = 0; half < 2; ++half) {
#pragma unroll
            for (int kk = 0; kk < 32; ++kk) {
                int koff = (half * 32 + kk) * 33 + lane;
                unsigned long long wp = wPp[koff];
                unsigned long long wc = wPc[koff];
                unsigned long long wn = wNp[koff];
                unsigned long long wq = wNc[koff];
#pragma unroll
                for (int r = 0; r < NODES; ++r) {
                    float xa = __shfl_sync(FULL, half ? x1v[r] : x0v[r], kk);
                    float pa = __shfl_sync(FULL, half ? p1v[r] : p0v[r], kk);
                    float na = __shfl_sync(FULL, half ? n1v[r] : n0v[r], kk);
                    unsigned long long xa2 = pack2(xa);
                    unsigned long long pa2 = pack2(pa);
                    unsigned long long na2 = pack2(na);
                    aPp[r] = fma2(pa2, wp, aPp[r]);
                    aPc[r] = fma2(xa2, wc, aPc[r]);
                    aNp[r] = fma2(na2, wn, aNp[r]);
                    aNc[r] = fma2(xa2, wq, aNc[r]);
                }
            }
        }

#pragma unroll
        for (int r = 0; r < NODES; ++r) {
            float xn = fmaxf(sqrtf(wsum(x0v[r] * x0v[r] + x1v[r] * x1v[r])), 1e-15f);
            float pn = fmaxf(sqrtf(wsum(p0v[r] * p0v[r] + p1v[r] * p1v[r])), 1e-15f);
            float nn = fmaxf(sqrtf(wsum(n0v[r] * n0v[r] + n1v[r] * n1v[r])), 1e-15f);
            float2 Pp = unpack2(aPp[r]);
            float2 Pc = unpack2(aPc[r]);
            float2 Np = unpack2(aNp[r]);
            float2 Nc = unpack2(aNc[r]);
            float oP0, oP1, oN0, oN1;
            node_out(Pp.x, Pp.y, pn, Pc.x, Pc.y, xn, hbp0, hbp1, y2p, oP0, oP1);
            node_out(Np.x, Np.y, nn, Nc.x, Nc.y, xn, hbn0, hbn1, y2n, oN0, oN1);
            if (valid[r]) {
                long i = idx[r];
                out[i * 128 + lane]      = oP0;
                out[i * 128 + 32 + lane] = oP1;
                out[i * 128 + 64 + lane] = oN0;
                out[i * 128 + 96 + lane] = oN1;
            }
        }
    }
}

// ---------------------------------------------------------------------------
extern "C" void kernel_launch(void* const* d_in, const int* in_sizes, int n_in,
                              void* d_out, int out_size) {
    const float* x   = (const float*)d_in[0];
    const float* Wp  = (const float*)d_in[1];
    const float* Wpc = (const float*)d_in[2];
    const float* bpc = (const float*)d_in[3];
    const float* Wn  = (const float*)d_in[4];
    const float* Wnc = (const float*)d_in[5];
    const float* bnc = (const float*)d_in[6];
    const int* pei   = (const int*)d_in[7];
    const int* nei   = (const int*)d_in[8];
    float* out = (float*)d_out;

    int n = in_sizes[0] / 64;
    int E = in_sizes[7] / 2;

    void *psum_p, *psum_n, *pcnt_p, *pcnt_n;
    cudaGetSymbolAddress(&psum_p, g_sum_pos);
    cudaGetSymbolAddress(&psum_n, g_sum_neg);
    cudaGetSymbolAddress(&pcnt_p, g_cnt_pos);
    cudaGetSymbolAddress(&pcnt_n, g_cnt_neg);
    cudaMemsetAsync(psum_p, 0, (size_t)n * 64 * sizeof(float));
    cudaMemsetAsync(psum_n, 0, (size_t)n * 64 * sizeof(float));
    cudaMemsetAsync(pcnt_p, 0, (size_t)n * sizeof(float));
    cudaMemsetAsync(pcnt_n, 0, (size_t)n * sizeof(float));

    bias_kernel<<<1, 32>>>(bpc, bnc);

    long work = 2L * E * 16;
    int thr = 256;
    int blocks = (int)((work + thr - 1) / thr);
    scatter_kernel<<<blocks, thr>>>(x, pei, nei,
                                    (float*)psum_p, (float*)psum_n,
                                    (float*)pcnt_p, (float*)pcnt_n, E);

    const int SMEM = 4 * 2112 * (int)sizeof(float2); // 67,584 B
    cudaFuncSetAttribute(compute_kernel, cudaFuncAttributeMaxDynamicSharedMemorySize, SMEM);
    compute_kernel<<<592, 256, SMEM>>>(x, Wp, Wpc, Wn, Wnc, out, n);
}

// round 5
// speedup vs baseline: 1.3846x; 1.3846x over previous
#include <cuda_runtime.h>
#include <cstdint>

#define NN 100096
#define FF 64
#define EB 128   // edges per scatter block

// ---------------- scratch (device globals: no runtime allocation) ----------
__device__ float g_sum_pos[(size_t)NN * FF];
__device__ float g_sum_neg[(size_t)NN * FF];
__device__ float g_cnt_pos[NN];
__device__ float g_cnt_neg[NN];
__device__ float g_mv[(size_t)NN * 256];   // matvec results: [node][Pp|Pc|Np|Nc]
__device__ float g_hb[136];                // hb_pos, hb_neg, y2_pos, y2_neg

__device__ __forceinline__ float wsum(float v) {
#pragma unroll
    for (int o = 16; o > 0; o >>= 1) v += __shfl_xor_sync(0xffffffffu, v, o);
    return v;
}

// packed f32x2 helpers (sm_103a)
__device__ __forceinline__ unsigned long long fma2(unsigned long long a,
                                                   unsigned long long b,
                                                   unsigned long long c) {
    unsigned long long d;
    asm("fma.rn.f32x2 %0, %1, %2, %3;" : "=l"(d) : "l"(a), "l"(b), "l"(c));
    return d;
}
__device__ __forceinline__ unsigned long long pack2(float v) {
    unsigned long long d;
    asm("mov.b64 %0, {%1, %1};" : "=l"(d) : "r"(__float_as_uint(v)));
    return d;
}

// ---------------- hyperbolic bias precompute: proj(expmap0(b, c=1)) --------
__global__ void bias_kernel(const float* __restrict__ bp, const float* __restrict__ bn) {
    int lane = threadIdx.x;
    if (lane >= 32) return;
    const float* bs[2] = {bp, bn};
#pragma unroll
    for (int i = 0; i < 2; ++i) {
        float u0 = bs[i][lane], u1 = bs[i][lane + 32];
        float n = fmaxf(sqrtf(wsum(u0 * u0 + u1 * u1)), 1e-15f);
        float s = tanhf(n) / n;
        float v0 = u0 * s, v1 = u1 * s;
        float vn = fmaxf(sqrtf(wsum(v0 * v0 + v1 * v1)), 1e-15f);
        if (vn > 0.996f) { float p = 0.996f / vn; v0 *= p; v1 *= p; }
        g_hb[i * 64 + lane]      = v0;
        g_hb[i * 64 + 32 + lane] = v1;
        float y2 = wsum(v0 * v0 + v1 * v1);
        if (lane == 0) g_hb[128 + i] = y2;
    }
}

// ---------------- scatter: smem-staged indices, 16 threads/edge ------------
__global__ void scatter_kernel(const float* __restrict__ x,
                               const int* __restrict__ pei, const int* __restrict__ nei,
                               float* __restrict__ sp, float* __restrict__ sn,
                               float* __restrict__ cp, float* __restrict__ cn, int E) {
    __shared__ int s_src[EB], s_dst[EB];
    const int* ei = blockIdx.y ? nei : pei;
    float* sum = blockIdx.y ? sn : sp;
    float* cnt = blockIdx.y ? cn : cp;
    long base = (long)blockIdx.x * EB;
    int tid = threadIdx.x;
    if (tid < EB) {
        long e = base + tid;
        s_src[tid] = (e < E) ? ei[e] : -1;
    } else {
        long e = base + (tid - EB);
        s_dst[tid - EB] = (e < E) ? ei[(long)E + e] : -1;
    }
    __syncthreads();
    int ch = tid & 15, eg = tid >> 4;   // 16 edges in flight, 16B chunk each
#pragma unroll
    for (int it = 0; it < EB / 16; ++it) {
        int e = it * 16 + eg;
        int dst = s_dst[e];
        if (dst < 0) continue;
        int src = s_src[e];
        float4 v = *reinterpret_cast<const float4*>(x + (size_t)src * FF + ch * 4);
        float* a = sum + (size_t)dst * FF + ch * 4;
        asm volatile("red.global.add.v4.f32 [%0], {%1,%2,%3,%4};"
                     :: "l"(a), "f"(v.x), "f"(v.y), "f"(v.z), "f"(v.w) : "memory");
        if (ch == 0)
            asm volatile("red.global.add.f32 [%0], %1;" :: "l"(cnt + dst), "f"(1.0f) : "memory");
    }
}

// ---------------- GEMM: g_mv[node][m*64+o] = sum_k W_m[o][k] * v_m[node][k] -
// block: 256 nodes x one matrix m. thread: og=tid&7 (8 outputs), ng=tid>>3 (8 nodes)
__global__ void __launch_bounds__(256, 2)
gemm_kernel(const float* __restrict__ x,
            const float* __restrict__ Wp,  const float* __restrict__ Wpc,
            const float* __restrict__ Wn,  const float* __restrict__ Wnc,
            float* __restrict__ mv, int n) {
    extern __shared__ float sh[];
    float* sA = sh;              // [64][256] transposed node vectors, 64KB
    float* sW = sh + 64 * 256;   // [64][68]  transposed weights, 17.4KB

    int m = blockIdx.y;
    const float* W = (m == 0) ? Wp : (m == 1) ? Wpc : (m == 2) ? Wn : Wnc;
    long node0 = (long)blockIdx.x * 256;
    int tid = threadIdx.x;

    // stage W transposed: sW[k*68+o] = W[o*64+k]
#pragma unroll
    for (int p = 0; p < 16; ++p) {
        int idx = p * 256 + tid;
        int o = idx >> 6, k = idx & 63;
        sW[k * 68 + o] = W[o * 64 + k];
    }
    // stage A transposed with mean-scaling folded in
    {
        int nl = tid & 63;
        int kc = tid >> 6;   // 0..3
#pragma unroll
        for (int q = 0; q < 4; ++q) {
            int node = q * 64 + nl;
            long gn = node0 + node;
            bool ok = gn < n;
            long gc = ok ? gn : 0;
            const float* srcv;
            float scale = 1.0f;
            if (m == 1 || m == 3) srcv = x;
            else if (m == 0) { srcv = g_sum_pos; scale = 1.0f / fmaxf(g_cnt_pos[gc], 1.0f); }
            else             { srcv = g_sum_neg; scale = 1.0f / fmaxf(g_cnt_neg[gc], 1.0f); }
            const float4* row = reinterpret_cast<const float4*>(srcv + gc * 64);
#pragma unroll
            for (int pk = 0; pk < 4; ++pk) {
                int k4 = kc + 4 * pk;
                float4 v = ok ? row[k4] : make_float4(0.f, 0.f, 0.f, 0.f);
                sA[(4 * k4 + 0) * 256 + node] = v.x * scale;
                sA[(4 * k4 + 1) * 256 + node] = v.y * scale;
                sA[(4 * k4 + 2) * 256 + node] = v.z * scale;
                sA[(4 * k4 + 3) * 256 + node] = v.w * scale;
            }
        }
    }
    __syncthreads();

    int og = tid & 7, ng = tid >> 3;   // ng 0..31
    unsigned long long acc[8][4];
#pragma unroll
    for (int i = 0; i < 8; ++i)
#pragma unroll
        for (int j = 0; j < 4; ++j) acc[i][j] = 0ull;

#pragma unroll 4
    for (int k = 0; k < 64; ++k) {
        float4 a0 = *reinterpret_cast<const float4*>(&sA[k * 256 + 4 * ng]);
        float4 a1 = *reinterpret_cast<const float4*>(&sA[k * 256 + 128 + 4 * ng]);
        ulonglong2 w0 = *reinterpret_cast<const ulonglong2*>(&sW[k * 68 + 8 * og]);
        ulonglong2 w1 = *reinterpret_cast<const ulonglong2*>(&sW[k * 68 + 8 * og + 4]);
        unsigned long long wv0 = w0.x, wv1 = w0.y, wv2 = w1.x, wv3 = w1.y;
        float av[8] = {a0.x, a0.y, a0.z, a0.w, a1.x, a1.y, a1.z, a1.w};
#pragma unroll
        for (int i = 0; i < 8; ++i) {
            unsigned long long p2 = pack2(av[i]);
            acc[i][0] = fma2(p2, wv0, acc[i][0]);
            acc[i][1] = fma2(p2, wv1, acc[i][1]);
            acc[i][2] = fma2(p2, wv2, acc[i][2]);
            acc[i][3] = fma2(p2, wv3, acc[i][3]);
        }
    }

#pragma unroll
    for (int i = 0; i < 8; ++i) {
        int node = (i < 4) ? (4 * ng + i) : (128 + 4 * ng + (i - 4));
        long gn = node0 + node;
        if (gn < n) {
            ulonglong2* dst = reinterpret_cast<ulonglong2*>(mv + gn * 256 + m * 64 + 8 * og);
            dst[0] = make_ulonglong2(acc[i][0], acc[i][1]);
            dst[1] = make_ulonglong2(acc[i][2], acc[i][3]);
        }
    }
}

// ---------------- hyperbolic epilogue (warp per node) ----------------------
__device__ __forceinline__ void matvec_proj(float m0, float m1, float xn,
                                            float& r0, float& r1) {
    float msq = wsum(m0 * m0 + m1 * m1);
    float mn = fmaxf(sqrtf(msq), 1e-15f);
    float art = atanhf(fminf(xn, 1.0f - 1e-7f));
    float sc = tanhf(mn / xn * art) / mn;
    r0 = m0 * sc; r1 = m1 * sc;
    float rsq = wsum(r0 * r0 + r1 * r1);
    float rn = fmaxf(sqrtf(rsq), 1e-15f);
    if (rn > 0.996f) { float s = 0.996f / rn; r0 *= s; r1 *= s; }
}

__device__ __forceinline__ void node_out(
    float aP0, float aP1, float pn,
    float aC0, float aC1, float xn,
    float hb0, float hb1, float y2,
    float& o0, float& o1) {
    float r0, r1; matvec_proj(aP0, aP1, pn, r0, r1);
    float s0, s1; matvec_proj(aC0, aC1, xn, s0, s1);
    float x2 = wsum(s0 * s0 + s1 * s1);
    float xy = wsum(s0 * hb0 + s1 * hb1);
    float f1 = 1.0f + 2.0f * xy + y2;
    float f2 = 1.0f - x2;
    float den = fmaxf(1.0f + 2.0f * xy + x2 * y2, 1e-15f);
    float q0 = (f1 * s0 + f2 * hb0) / den;
    float q1 = (f1 * s1 + f2 * hb1) / den;
    float qn = fmaxf(sqrtf(wsum(q0 * q0 + q1 * q1)), 1e-15f);
    if (qn > 0.996f) { float p = 0.996f / qn; q0 *= p; q1 *= p; }
    o0 = r0 + q0; o1 = r1 + q1;
}

__global__ void epilogue_kernel(const float* __restrict__ x,
                                float* __restrict__ out, int n) {
    long w = (long)(blockIdx.x * blockDim.x + threadIdx.x) >> 5;
    int lane = threadIdx.x & 31;
    if (w >= n) return;

    const float* row = g_mv + (size_t)w * 256;
    float Pp0 = row[lane],       Pp1 = row[32 + lane];
    float Pc0 = row[64 + lane],  Pc1 = row[96 + lane];
    float Np0 = row[128 + lane], Np1 = row[160 + lane];
    float Nc0 = row[192 + lane], Nc1 = row[224 + lane];

    float x0 = x[w * 64 + lane], x1 = x[w * 64 + 32 + lane];
    float rp = 1.0f / fmaxf(g_cnt_pos[w], 1.0f);
    float rn = 1.0f / fmaxf(g_cnt_neg[w], 1.0f);
    float p0 = g_sum_pos[w * 64 + lane] * rp, p1 = g_sum_pos[w * 64 + 32 + lane] * rp;
    float q0 = g_sum_neg[w * 64 + lane] * rn, q1 = g_sum_neg[w * 64 + 32 + lane] * rn;

    float xn = fmaxf(sqrtf(wsum(x0 * x0 + x1 * x1)), 1e-15f);
    float pn = fmaxf(sqrtf(wsum(p0 * p0 + p1 * p1)), 1e-15f);
    float nn = fmaxf(sqrtf(wsum(q0 * q0 + q1 * q1)), 1e-15f);

    float hbp0 = g_hb[lane],      hbp1 = g_hb[32 + lane];
    float hbn0 = g_hb[64 + lane], hbn1 = g_hb[96 + lane];
    float y2p = g_hb[128], y2n = g_hb[129];

    float oP0, oP1, oN0, oN1;
    node_out(Pp0, Pp1, pn, Pc0, Pc1, xn, hbp0, hbp1, y2p, oP0, oP1);
    node_out(Np0, Np1, nn, Nc0, Nc1, xn, hbn0, hbn1, y2n, oN0, oN1);

    out[w * 128 + lane]      = oP0;
    out[w * 128 + 32 + lane] = oP1;
    out[w * 128 + 64 + lane] = oN0;
    out[w * 128 + 96 + lane] = oN1;
}

// ---------------------------------------------------------------------------
extern "C" void kernel_launch(void* const* d_in, const int* in_sizes, int n_in,
                              void* d_out, int out_size) {
    const float* x   = (const float*)d_in[0];
    const float* Wp  = (const float*)d_in[1];
    const float* Wpc = (const float*)d_in[2];
    const float* bpc = (const float*)d_in[3];
    const float* Wn  = (const float*)d_in[4];
    const float* Wnc = (const float*)d_in[5];
    const float* bnc = (const float*)d_in[6];
    const int* pei   = (const int*)d_in[7];
    const int* nei   = (const int*)d_in[8];
    float* out = (float*)d_out;

    int n = in_sizes[0] / 64;
    int E = in_sizes[7] / 2;

    void *psum_p, *psum_n, *pcnt_p, *pcnt_n, *pmv;
    cudaGetSymbolAddress(&psum_p, g_sum_pos);
    cudaGetSymbolAddress(&psum_n, g_sum_neg);
    cudaGetSymbolAddress(&pcnt_p, g_cnt_pos);
    cudaGetSymbolAddress(&pcnt_n, g_cnt_neg);
    cudaGetSymbolAddress(&pmv, g_mv);
    cudaMemsetAsync(psum_p, 0, (size_t)n * 64 * sizeof(float));
    cudaMemsetAsync(psum_n, 0, (size_t)n * 64 * sizeof(float));
    cudaMemsetAsync(pcnt_p, 0, (size_t)n * sizeof(float));
    cudaMemsetAsync(pcnt_n, 0, (size_t)n * sizeof(float));

    bias_kernel<<<1, 32>>>(bpc, bnc);

    dim3 sgrid((E + EB - 1) / EB, 2);
    scatter_kernel<<<sgrid, 256>>>(x, pei, nei,
                                   (float*)psum_p, (float*)psum_n,
                                   (float*)pcnt_p, (float*)pcnt_n, E);

    const int GSMEM = (64 * 256 + 64 * 68) * (int)sizeof(float); // 82,944 B
    cudaFuncSetAttribute(gemm_kernel, cudaFuncAttributeMaxDynamicSharedMemorySize, GSMEM);
    dim3 ggrid((n + 255) / 256, 4);
    gemm_kernel<<<ggrid, 256, GSMEM>>>(x, Wp, Wpc, Wn, Wnc, (float*)pmv, n);

    int eblocks = (int)(((long)n * 32 + 255) / 256);
    epilogue_kernel<<<eblocks, 256>>>(x, out, n);
}